// round 2
// baseline (speedup 1.0000x reference)
#include <cuda_runtime.h>
#include <cstdint>

// LightGCN propagation:
//   all_emb = concat(user_emb, item_emb)            [N_TOTAL, 64]
//   acc = all_emb; x = all_emb
//   3x: x = scatter_add(x[col] * w, row); acc += x
//   out = acc / 4
//
// N_USERS=100000, N_ITEMS=50000, N_TOTAL=150000, D=64, E=2000000

#define N_USERS   100000
#define N_ITEMS   50000
#define N_TOTAL   150000
#define EMB_DIM   64
#define N_EDGES   2000000
#define N_ELEMS   (N_TOTAL * EMB_DIM)        // 9,600,000 floats
#define N_F4      (N_ELEMS / 4)              // 2,400,000 float4

// Scratch node-feature buffers (38.4 MB each) — both fit in L2 together.
// Declared as float4 so the 16B-vector atomics are guaranteed aligned.
__device__ float4 g_bufA[N_F4];
__device__ float4 g_bufB[N_F4];

// 1 if edge_index is int64, 0 if int32 (JAX default x64-disabled downcasts
// jnp.int64 -> int32 silently; detect at runtime, on-device).
__device__ int g_idx_is64;

// ---------------------------------------------------------------------------
// detect dtype of edge_index: sample 256 entries as int64; valid int64 data
// has every value in [0, N_TOTAL). int32 data read as int64 fuses two random
// indices -> huge values -> fails the range check.
// ---------------------------------------------------------------------------
__global__ void detect_kernel(const long long* __restrict__ edge_index64) {
    __shared__ int ok;
    if (threadIdx.x == 0) ok = 1;
    __syncthreads();
    long long v = edge_index64[threadIdx.x];   // first 256 of 2E entries
    if (v < 0 || v >= N_TOTAL) atomicAnd(&ok, 0);
    __syncthreads();
    if (threadIdx.x == 0) g_idx_is64 = ok;
}

// ---------------------------------------------------------------------------
// init: bufA = concat(user_emb, item_emb); acc(out) = same
// ---------------------------------------------------------------------------
__global__ void init_kernel(const float4* __restrict__ user,
                            const float4* __restrict__ item,
                            float4* __restrict__ out,
                            float4* __restrict__ bufA) {
    int i = blockIdx.x * blockDim.x + threadIdx.x;
    if (i >= N_F4) return;
    const int USER_F4 = (N_USERS * EMB_DIM) / 4;
    float4 v = (i < USER_F4) ? user[i] : item[i - USER_F4];
    bufA[i] = v;
    out[i]  = v;
}

// ---------------------------------------------------------------------------
// zero a buffer
// ---------------------------------------------------------------------------
__global__ void zero_kernel(float4* __restrict__ buf) {
    int i = blockIdx.x * blockDim.x + threadIdx.x;
    if (i >= N_F4) return;
    buf[i] = make_float4(0.f, 0.f, 0.f, 0.f);
}

// ---------------------------------------------------------------------------
// scatter: for each edge e: xn[row[e]] += x[col[e]] * w[e]
// 16 threads per edge, one float4 each (row is 16 float4s = 256B).
// Half-warp lanes read consecutive float4s of the same (random) source row:
// a single coalesced 256B L2 transaction. Destination update via
// red.global.add.v4.f32 (vectorized fire-and-forget L2 atomic, sm_90+).
// ---------------------------------------------------------------------------
__global__ void scatter_kernel(const void* __restrict__ edge_index,
                               const float* __restrict__ edge_weight,
                               const float4* __restrict__ x,
                               float4* __restrict__ xn) {
    long long gid = (long long)blockIdx.x * blockDim.x + threadIdx.x;
    int e = (int)(gid >> 4);
    int j = (int)(gid & 15);
    if (e >= N_EDGES) return;

    int r, c;
    if (__ldg(&g_idx_is64)) {
        const long long* ei = (const long long*)edge_index;
        r = (int)__ldg(&ei[e]);
        c = (int)__ldg(&ei[N_EDGES + e]);
    } else {
        const int* ei = (const int*)edge_index;
        r = __ldg(&ei[e]);
        c = __ldg(&ei[N_EDGES + e]);
    }
    float w = __ldg(&edge_weight[e]);

    float4 v = __ldg(&x[(long long)c * 16 + j]);
    float4 m = make_float4(v.x * w, v.y * w, v.z * w, v.w * w);

    float* dst = (float*)(xn + (long long)r * 16 + j);
    asm volatile("red.global.add.v4.f32 [%0], {%1, %2, %3, %4};"
                 :: "l"(dst), "f"(m.x), "f"(m.y), "f"(m.z), "f"(m.w)
                 : "memory");
}

// ---------------------------------------------------------------------------
// acc += xn, and zero the other buffer for the next layer's scatter target
// ---------------------------------------------------------------------------
__global__ void add_and_zero_kernel(float4* __restrict__ acc,
                                    const float4* __restrict__ xn,
                                    float4* __restrict__ zbuf) {
    int i = blockIdx.x * blockDim.x + threadIdx.x;
    if (i >= N_F4) return;
    float4 a = acc[i];
    float4 b = xn[i];
    acc[i] = make_float4(a.x + b.x, a.y + b.y, a.z + b.z, a.w + b.w);
    zbuf[i] = make_float4(0.f, 0.f, 0.f, 0.f);
}

// ---------------------------------------------------------------------------
// final: out = (out + xn) * 0.25
// ---------------------------------------------------------------------------
__global__ void final_kernel(float4* __restrict__ acc,
                             const float4* __restrict__ xn) {
    int i = blockIdx.x * blockDim.x + threadIdx.x;
    if (i >= N_F4) return;
    float4 a = acc[i];
    float4 b = xn[i];
    acc[i] = make_float4((a.x + b.x) * 0.25f, (a.y + b.y) * 0.25f,
                         (a.z + b.z) * 0.25f, (a.w + b.w) * 0.25f);
}

extern "C" void kernel_launch(void* const* d_in, const int* in_sizes, int n_in,
                              void* d_out, int out_size) {
    const void* edge_index   = d_in[0];                 // [2, E] int32 or int64
    const float* edge_weight = (const float*)d_in[1];   // [E]
    const float* user_emb    = (const float*)d_in[2];   // [N_USERS, 64]
    const float* item_emb    = (const float*)d_in[3];   // [N_ITEMS, 64]
    float* out               = (float*)d_out;           // [N_TOTAL, 64]

    float4* bufA;
    float4* bufB;
    cudaGetSymbolAddress((void**)&bufA, g_bufA);
    cudaGetSymbolAddress((void**)&bufB, g_bufB);

    const int TPB = 256;
    const int GRID_ELEM = (N_F4 + TPB - 1) / TPB;
    const long long scatter_threads = (long long)N_EDGES * 16;
    const int GRID_SCAT = (int)((scatter_threads + TPB - 1) / TPB);

    // Detect edge_index dtype (writes g_idx_is64; deterministic every call)
    detect_kernel<<<1, 256>>>((const long long*)edge_index);

    // Layer 0: bufA = all_emb, acc = all_emb
    init_kernel<<<GRID_ELEM, TPB>>>((const float4*)user_emb,
                                    (const float4*)item_emb,
                                    (float4*)out, bufA);
    zero_kernel<<<GRID_ELEM, TPB>>>(bufB);

    // Layer 1: bufB = scatter(bufA); acc += bufB; zero bufA
    scatter_kernel<<<GRID_SCAT, TPB>>>(edge_index, edge_weight, bufA, bufB);
    add_and_zero_kernel<<<GRID_ELEM, TPB>>>((float4*)out, bufB, bufA);

    // Layer 2: bufA = scatter(bufB); acc += bufA; zero bufB
    scatter_kernel<<<GRID_SCAT, TPB>>>(edge_index, edge_weight, bufB, bufA);
    add_and_zero_kernel<<<GRID_ELEM, TPB>>>((float4*)out, bufA, bufB);

    // Layer 3: bufB = scatter(bufA); out = (acc + bufB) / 4
    scatter_kernel<<<GRID_SCAT, TPB>>>(edge_index, edge_weight, bufA, bufB);
    final_kernel<<<GRID_ELEM, TPB>>>((float4*)out, bufB);
}

// round 3
// speedup vs baseline: 1.8243x; 1.8243x over previous
#include <cuda_runtime.h>
#include <cstdint>

// LightGCN propagation, pull formulation:
//   CSR-sort edges by destination row (once per call, device-side),
//   then 3 pull layers: x_new[n] = sum_{e in row n} x[col[e]] * w[e]
//   acc += x_new fused into pull epilogue; final layer fuses *0.25.

#define N_USERS   100000
#define N_ITEMS   50000
#define N_TOTAL   150000
#define EMB_DIM   64
#define N_EDGES   2000000
#define N_ELEMS   (N_TOTAL * EMB_DIM)
#define N_F4      (N_ELEMS / 4)

#define SCAN_BLK  1024
#define N_SCANBLK ((N_TOTAL + SCAN_BLK - 1) / SCAN_BLK)   // 147

// feature double-buffer (38.4 MB each, both L2-resident together with CSR)
__device__ float4 g_bufA[N_F4];
__device__ float4 g_bufB[N_F4];

// CSR scratch
__device__ int   g_deg[N_TOTAL];
__device__ int   g_incl[N_TOTAL];          // per-block inclusive scans
__device__ int   g_off[N_TOTAL + 1];       // exclusive offsets
__device__ int   g_cursor[N_TOTAL];        // fill cursors
__device__ int   g_partials[N_SCANBLK];
__device__ int   g_blockoff[N_SCANBLK];
__device__ int   g_col[N_EDGES];           // sorted-by-row col indices
__device__ float g_w[N_EDGES];             // sorted-by-row weights

__device__ int   g_idx_is64;               // edge_index dtype flag

// ---------------------------------------------------------------------------
// dtype detect: int64 data has all sampled values in [0, N_TOTAL);
// int32 data read as int64 fuses two random indices -> out of range.
// ---------------------------------------------------------------------------
__global__ void detect_kernel(const long long* __restrict__ ei64) {
    __shared__ int ok;
    if (threadIdx.x == 0) ok = 1;
    __syncthreads();
    long long v = ei64[threadIdx.x];
    if (v < 0 || v >= N_TOTAL) atomicAnd(&ok, 0);
    __syncthreads();
    if (threadIdx.x == 0) g_idx_is64 = ok;
}

// ---------------------------------------------------------------------------
// init: bufA = concat(user, item); out(acc) = same; zero degree histogram
// ---------------------------------------------------------------------------
__global__ void init_kernel(const float4* __restrict__ user,
                            const float4* __restrict__ item,
                            float4* __restrict__ out,
                            float4* __restrict__ bufA) {
    int i = blockIdx.x * blockDim.x + threadIdx.x;
    if (i < N_TOTAL) g_deg[i] = 0;
    if (i >= N_F4) return;
    const int USER_F4 = (N_USERS * EMB_DIM) / 4;
    float4 v = (i < USER_F4) ? user[i] : item[i - USER_F4];
    bufA[i] = v;
    out[i]  = v;
}

// ---------------------------------------------------------------------------
// histogram of destination rows
// ---------------------------------------------------------------------------
__global__ void hist_kernel(const void* __restrict__ edge_index) {
    int e = blockIdx.x * blockDim.x + threadIdx.x;
    if (e >= N_EDGES) return;
    int r;
    if (__ldg(&g_idx_is64)) r = (int)__ldg(&((const long long*)edge_index)[e]);
    else                    r = __ldg(&((const int*)edge_index)[e]);
    atomicAdd(&g_deg[r], 1);
}

// ---------------------------------------------------------------------------
// 3-kernel exclusive scan of g_deg -> g_off (+ cursors)
// ---------------------------------------------------------------------------
__global__ void scan1_kernel() {
    __shared__ int sh[SCAN_BLK];
    int i = blockIdx.x * SCAN_BLK + threadIdx.x;
    int v = (i < N_TOTAL) ? g_deg[i] : 0;
    sh[threadIdx.x] = v;
    __syncthreads();
    for (int off = 1; off < SCAN_BLK; off <<= 1) {
        int t = (threadIdx.x >= off) ? sh[threadIdx.x - off] : 0;
        __syncthreads();
        sh[threadIdx.x] += t;
        __syncthreads();
    }
    if (i < N_TOTAL) g_incl[i] = sh[threadIdx.x];
    if (threadIdx.x == SCAN_BLK - 1) g_partials[blockIdx.x] = sh[SCAN_BLK - 1];
}

__global__ void scan2_kernel() {
    if (threadIdx.x == 0) {
        int run = 0;
        for (int b = 0; b < N_SCANBLK; b++) {
            g_blockoff[b] = run;
            run += g_partials[b];
        }
    }
}

__global__ void scan3_kernel() {
    int i = blockIdx.x * blockDim.x + threadIdx.x;
    if (i >= N_TOTAL) return;
    int incl = g_incl[i] + g_blockoff[i / SCAN_BLK];
    g_off[i + 1] = incl;                  // inclusive -> off[i+1]
    g_cursor[i]  = incl - g_deg[i];       // exclusive start
    if (i == 0) g_off[0] = 0;
}

// ---------------------------------------------------------------------------
// fill sorted edge arrays
// ---------------------------------------------------------------------------
__global__ void fill_kernel(const void* __restrict__ edge_index,
                            const float* __restrict__ edge_weight) {
    int e = blockIdx.x * blockDim.x + threadIdx.x;
    if (e >= N_EDGES) return;
    int r, c;
    if (__ldg(&g_idx_is64)) {
        const long long* ei = (const long long*)edge_index;
        r = (int)__ldg(&ei[e]);
        c = (int)__ldg(&ei[N_EDGES + e]);
    } else {
        const int* ei = (const int*)edge_index;
        r = __ldg(&ei[e]);
        c = __ldg(&ei[N_EDGES + e]);
    }
    int p = atomicAdd(&g_cursor[r], 1);
    g_col[p] = c;
    g_w[p]   = __ldg(&edge_weight[e]);
}

// ---------------------------------------------------------------------------
// pull: 16 threads per node, thread j owns float4 lane j of the node row.
// Accumulate sum over in-edges in registers; zero atomics.
// Epilogue: FINAL=0 -> xn[n]=a, out[n]+=a ; FINAL=1 -> out[n]=(out[n]+a)*0.25
// ---------------------------------------------------------------------------
template <int FINAL>
__global__ void pull_kernel(const float4* __restrict__ x,
                            float4* __restrict__ xn,
                            float4* __restrict__ out) {
    int gid = blockIdx.x * blockDim.x + threadIdx.x;
    int n = gid >> 4;
    int j = gid & 15;
    if (n >= N_TOTAL) return;

    int s = __ldg(&g_off[n]);
    int t = __ldg(&g_off[n + 1]);

    float4 a = make_float4(0.f, 0.f, 0.f, 0.f);
    int e = s;
    // unroll-by-2 for memory-level parallelism
    for (; e + 2 <= t; e += 2) {
        int   c0 = __ldg(&g_col[e]);
        int   c1 = __ldg(&g_col[e + 1]);
        float w0 = __ldg(&g_w[e]);
        float w1 = __ldg(&g_w[e + 1]);
        float4 v0 = __ldg(&x[(long long)c0 * 16 + j]);
        float4 v1 = __ldg(&x[(long long)c1 * 16 + j]);
        a.x += v0.x * w0; a.y += v0.y * w0; a.z += v0.z * w0; a.w += v0.w * w0;
        a.x += v1.x * w1; a.y += v1.y * w1; a.z += v1.z * w1; a.w += v1.w * w1;
    }
    if (e < t) {
        int   c0 = __ldg(&g_col[e]);
        float w0 = __ldg(&g_w[e]);
        float4 v0 = __ldg(&x[(long long)c0 * 16 + j]);
        a.x += v0.x * w0; a.y += v0.y * w0; a.z += v0.z * w0; a.w += v0.w * w0;
    }

    long long oi = (long long)n * 16 + j;
    float4 o = out[oi];
    if (FINAL) {
        out[oi] = make_float4((o.x + a.x) * 0.25f, (o.y + a.y) * 0.25f,
                              (o.z + a.z) * 0.25f, (o.w + a.w) * 0.25f);
    } else {
        xn[oi] = a;
        out[oi] = make_float4(o.x + a.x, o.y + a.y, o.z + a.z, o.w + a.w);
    }
}

extern "C" void kernel_launch(void* const* d_in, const int* in_sizes, int n_in,
                              void* d_out, int out_size) {
    const void* edge_index   = d_in[0];
    const float* edge_weight = (const float*)d_in[1];
    const float* user_emb    = (const float*)d_in[2];
    const float* item_emb    = (const float*)d_in[3];
    float* out               = (float*)d_out;

    float4* bufA;
    float4* bufB;
    cudaGetSymbolAddress((void**)&bufA, g_bufA);
    cudaGetSymbolAddress((void**)&bufB, g_bufB);

    const int TPB = 256;
    const int GRID_INIT = (N_F4 + TPB - 1) / TPB;           // covers N_TOTAL too
    const int GRID_EDGE = (N_EDGES + TPB - 1) / TPB;
    const int GRID_NODE = (N_TOTAL + TPB - 1) / TPB;
    const int GRID_PULL = (N_TOTAL * 16 + TPB - 1) / TPB;

    detect_kernel<<<1, 256>>>((const long long*)edge_index);
    init_kernel<<<GRID_INIT, TPB>>>((const float4*)user_emb,
                                    (const float4*)item_emb,
                                    (float4*)out, bufA);

    // CSR build
    hist_kernel<<<GRID_EDGE, TPB>>>(edge_index);
    scan1_kernel<<<N_SCANBLK, SCAN_BLK>>>();
    scan2_kernel<<<1, 32>>>();
    scan3_kernel<<<GRID_NODE, TPB>>>();
    fill_kernel<<<GRID_EDGE, TPB>>>(edge_index, edge_weight);

    // 3 pull layers (acc update fused; final scale fused)
    pull_kernel<0><<<GRID_PULL, TPB>>>(bufA, bufB, (float4*)out);
    pull_kernel<0><<<GRID_PULL, TPB>>>(bufB, bufA, (float4*)out);
    pull_kernel<1><<<GRID_PULL, TPB>>>(bufA, bufB, (float4*)out);
}

// round 4
// speedup vs baseline: 2.1084x; 1.1558x over previous
#include <cuda_runtime.h>
#include <cstdint>

// LightGCN propagation, pull formulation with deferred accumulator:
//   CSR-sort edges by destination (device-side, per call), then
//   x1 = A x0 (gather straight from user/item inputs)
//   x2 = A x1
//   out = 0.25 * (x0 + x1 + x2 + A x2)   (fused into last pull epilogue)

#define N_USERS   100000
#define N_ITEMS   50000
#define N_TOTAL   150000
#define EMB_DIM   64
#define N_EDGES   2000000
#define N_ELEMS   (N_TOTAL * EMB_DIM)
#define N_F4      (N_ELEMS / 4)

#define SCAN_BLK  1024
#define N_SCANBLK ((N_TOTAL + SCAN_BLK - 1) / SCAN_BLK)   // 147

// feature buffers: x1, x2 (38.4 MB each)
__device__ float4 g_bufX1[N_F4];
__device__ float4 g_bufX2[N_F4];

// CSR scratch
__device__ int   g_deg[N_TOTAL];
__device__ int   g_incl[N_TOTAL];
__device__ int   g_off[N_TOTAL + 1];
__device__ int   g_cursor[N_TOTAL];
__device__ int   g_partials[N_SCANBLK];
__device__ int   g_blockoff[N_SCANBLK];
__device__ int2  g_cw[N_EDGES];            // packed {col, weight-bits}, row-sorted

__device__ int   g_idx_is64;

// ---------------------------------------------------------------------------
// dtype detect (block 0) + zero degree histogram (whole grid)
// ---------------------------------------------------------------------------
__global__ void detect_and_zero_kernel(const long long* __restrict__ ei64) {
    int i = blockIdx.x * blockDim.x + threadIdx.x;
    if (i < N_TOTAL) g_deg[i] = 0;
    if (blockIdx.x == 0) {
        __shared__ int ok;
        if (threadIdx.x == 0) ok = 1;
        __syncthreads();
        long long v = ei64[threadIdx.x];
        if (v < 0 || v >= N_TOTAL) atomicAnd(&ok, 0);
        __syncthreads();
        if (threadIdx.x == 0) g_idx_is64 = ok;
    }
}

// ---------------------------------------------------------------------------
// histogram of destination rows
// ---------------------------------------------------------------------------
__global__ void hist_kernel(const void* __restrict__ edge_index) {
    int e = blockIdx.x * blockDim.x + threadIdx.x;
    if (e >= N_EDGES) return;
    int r;
    if (__ldg(&g_idx_is64)) r = (int)__ldg(&((const long long*)edge_index)[e]);
    else                    r = __ldg(&((const int*)edge_index)[e]);
    atomicAdd(&g_deg[r], 1);
}

// ---------------------------------------------------------------------------
// 3-kernel exclusive scan of g_deg -> g_off (+ fill cursors)
// ---------------------------------------------------------------------------
__global__ void scan1_kernel() {
    __shared__ int sh[SCAN_BLK];
    int i = blockIdx.x * SCAN_BLK + threadIdx.x;
    int v = (i < N_TOTAL) ? g_deg[i] : 0;
    sh[threadIdx.x] = v;
    __syncthreads();
    for (int off = 1; off < SCAN_BLK; off <<= 1) {
        int t = (threadIdx.x >= off) ? sh[threadIdx.x - off] : 0;
        __syncthreads();
        sh[threadIdx.x] += t;
        __syncthreads();
    }
    if (i < N_TOTAL) g_incl[i] = sh[threadIdx.x];
    if (threadIdx.x == SCAN_BLK - 1) g_partials[blockIdx.x] = sh[SCAN_BLK - 1];
}

__global__ void scan2_kernel() {
    if (threadIdx.x == 0) {
        int run = 0;
        for (int b = 0; b < N_SCANBLK; b++) {
            g_blockoff[b] = run;
            run += g_partials[b];
        }
    }
}

__global__ void scan3_kernel() {
    int i = blockIdx.x * blockDim.x + threadIdx.x;
    if (i >= N_TOTAL) return;
    int incl = g_incl[i] + g_blockoff[i / SCAN_BLK];
    g_off[i + 1] = incl;
    g_cursor[i]  = incl - g_deg[i];
    if (i == 0) g_off[0] = 0;
}

// ---------------------------------------------------------------------------
// fill row-sorted packed edge array
// ---------------------------------------------------------------------------
__global__ void fill_kernel(const void* __restrict__ edge_index,
                            const float* __restrict__ edge_weight) {
    int e = blockIdx.x * blockDim.x + threadIdx.x;
    if (e >= N_EDGES) return;
    int r, c;
    if (__ldg(&g_idx_is64)) {
        const long long* ei = (const long long*)edge_index;
        r = (int)__ldg(&ei[e]);
        c = (int)__ldg(&ei[N_EDGES + e]);
    } else {
        const int* ei = (const int*)edge_index;
        r = __ldg(&ei[e]);
        c = __ldg(&ei[N_EDGES + e]);
    }
    int p = atomicAdd(&g_cursor[r], 1);
    g_cw[p] = make_int2(c, __float_as_int(__ldg(&edge_weight[e])));
}

// ---------------------------------------------------------------------------
// pull: 16 threads per node (thread j = float4 lane j), register accumulate.
// FIRST: gather source is the split user/item input pair (x0 unmaterialized).
// FINAL: epilogue fuses out = 0.25 * (x0 + x1 + x2 + a).
// ---------------------------------------------------------------------------
template <int FIRST, int FINAL>
__global__ void pull_kernel(const float4* __restrict__ gu,   // gather base (user / buf)
                            const float4* __restrict__ gi,   // gather base item, pre-offset
                            float4* __restrict__ xn,         // output buffer (FINAL=0)
                            const float4* __restrict__ eu,   // epilogue x0 user
                            const float4* __restrict__ ei,   // epilogue x0 item
                            const float4* __restrict__ x1,
                            const float4* __restrict__ x2,
                            float4* __restrict__ out) {
    int gid = blockIdx.x * blockDim.x + threadIdx.x;
    int n = gid >> 4;
    int j = gid & 15;
    if (n >= N_TOTAL) return;

    int s = __ldg(&g_off[n]);
    int t = __ldg(&g_off[n + 1]);

    float4 a = make_float4(0.f, 0.f, 0.f, 0.f);
    int e = s;

#define EDGE_STEP(K)                                                          \
    {                                                                         \
        int2 cw = __ldg(&g_cw[e + K]);                                        \
        int c = cw.x;                                                         \
        float w = __int_as_float(cw.y);                                       \
        const float4* base = (FIRST && c >= N_USERS) ? gi : gu;               \
        float4 v = __ldg(base + (long long)c * 16 + j);                       \
        a.x += v.x * w; a.y += v.y * w; a.z += v.z * w; a.w += v.w * w;       \
    }

    for (; e + 4 <= t; e += 4) {
        EDGE_STEP(0) EDGE_STEP(1) EDGE_STEP(2) EDGE_STEP(3)
    }
    for (; e < t; e++) {
        EDGE_STEP(0)
    }
#undef EDGE_STEP

    long long oi = (long long)n * 16 + j;
    if (FINAL) {
        float4 x0 = (n < N_USERS)
                        ? __ldg(&eu[oi])
                        : __ldg(&ei[(long long)(n - N_USERS) * 16 + j]);
        float4 v1 = __ldg(&x1[oi]);
        float4 v2 = __ldg(&x2[oi]);
        out[oi] = make_float4((x0.x + v1.x + v2.x + a.x) * 0.25f,
                              (x0.y + v1.y + v2.y + a.y) * 0.25f,
                              (x0.z + v1.z + v2.z + a.z) * 0.25f,
                              (x0.w + v1.w + v2.w + a.w) * 0.25f);
    } else {
        xn[oi] = a;
    }
}

extern "C" void kernel_launch(void* const* d_in, const int* in_sizes, int n_in,
                              void* d_out, int out_size) {
    const void* edge_index   = d_in[0];
    const float* edge_weight = (const float*)d_in[1];
    const float4* user_emb   = (const float4*)d_in[2];
    const float4* item_emb   = (const float4*)d_in[3];
    float4* out              = (float4*)d_out;

    float4* x1;
    float4* x2;
    cudaGetSymbolAddress((void**)&x1, g_bufX1);
    cudaGetSymbolAddress((void**)&x2, g_bufX2);

    const int TPB = 256;
    const int GRID_NODE = (N_TOTAL + TPB - 1) / TPB;
    const int GRID_EDGE = (N_EDGES + TPB - 1) / TPB;
    const int GRID_PULL = (N_TOTAL * 16 + TPB - 1) / TPB;

    // item gather base pre-offset so global index c works directly
    const float4* item_adj = item_emb - (long long)N_USERS * 16;

    detect_and_zero_kernel<<<GRID_NODE, TPB>>>((const long long*)edge_index);

    // CSR build
    hist_kernel<<<GRID_EDGE, TPB>>>(edge_index);
    scan1_kernel<<<N_SCANBLK, SCAN_BLK>>>();
    scan2_kernel<<<1, 32>>>();
    scan3_kernel<<<GRID_NODE, TPB>>>();
    fill_kernel<<<GRID_EDGE, TPB>>>(edge_index, edge_weight);

    // x1 = A x0  (x0 read directly from inputs)
    pull_kernel<1, 0><<<GRID_PULL, TPB>>>(user_emb, item_adj, x1,
                                          nullptr, nullptr, nullptr, nullptr,
                                          nullptr);
    // x2 = A x1
    pull_kernel<0, 0><<<GRID_PULL, TPB>>>(x1, x1, x2,
                                          nullptr, nullptr, nullptr, nullptr,
                                          nullptr);
    // out = 0.25 * (x0 + x1 + x2 + A x2)
    pull_kernel<0, 1><<<GRID_PULL, TPB>>>(x2, x2, nullptr,
                                          user_emb, item_emb, x1, x2, out);
}

// round 5
// speedup vs baseline: 2.8031x; 1.3295x over previous
#include <cuda_runtime.h>
#include <cuda_fp16.h>
#include <cstdint>

// LightGCN propagation, pull formulation, fp16 feature storage / fp32 accum:
//   h0 = fp16(concat(user, item))
//   h1 = fp16(A h0) ; h2 = fp16(A h1)
//   out = 0.25 * (x0_fp32 + h1 + h2 + A h2)     (final pull epilogue, fp32 out)

#define N_USERS   100000
#define N_ITEMS   50000
#define N_TOTAL   150000
#define EMB_DIM   64
#define N_EDGES   2000000
#define N_ELEMS   (N_TOTAL * EMB_DIM)
#define N_F4      (N_ELEMS / 4)            // 2,400,000 (float4 / uint2 units)

#define SCAN_BLK  1024
#define N_SCANBLK ((N_TOTAL + SCAN_BLK - 1) / SCAN_BLK)   // 147

// fp16 feature buffers: 64 halves = 16 uint2 per row (19.2 MB each)
__device__ uint2 g_h0[N_F4];
__device__ uint2 g_h1[N_F4];
__device__ uint2 g_h2[N_F4];

// CSR scratch
__device__ int   g_deg[N_TOTAL];
__device__ int   g_incl[N_TOTAL];
__device__ int   g_off[N_TOTAL + 1];
__device__ int   g_cursor[N_TOTAL];
__device__ int   g_partials[N_SCANBLK];
__device__ int   g_blockoff[N_SCANBLK];
__device__ int2  g_cw[N_EDGES];            // packed {col, weight-bits}, row-sorted

__device__ int   g_idx_is64;

// ---------------------------------------------------------------------------
// pack 4 floats -> uint2 of two half2
// ---------------------------------------------------------------------------
__device__ __forceinline__ uint2 pack_h4(float4 v) {
    __half2 a = __float22half2_rn(make_float2(v.x, v.y));
    __half2 b = __float22half2_rn(make_float2(v.z, v.w));
    uint2 r;
    r.x = *(unsigned int*)&a;
    r.y = *(unsigned int*)&b;
    return r;
}

// ---------------------------------------------------------------------------
// dtype detect (block 0) + zero histogram + convert x0 -> fp16
// ---------------------------------------------------------------------------
__global__ void prep_kernel(const long long* __restrict__ ei64,
                            const float4* __restrict__ user,
                            const float4* __restrict__ item) {
    int i = blockIdx.x * blockDim.x + threadIdx.x;
    if (i < N_TOTAL) g_deg[i] = 0;
    if (i < N_F4) {
        const int USER_F4 = (N_USERS * EMB_DIM) / 4;
        float4 v = (i < USER_F4) ? __ldg(&user[i]) : __ldg(&item[i - USER_F4]);
        g_h0[i] = pack_h4(v);
    }
    if (blockIdx.x == 0) {
        __shared__ int ok;
        if (threadIdx.x == 0) ok = 1;
        __syncthreads();
        long long v = ei64[threadIdx.x];
        if (v < 0 || v >= N_TOTAL) atomicAnd(&ok, 0);
        __syncthreads();
        if (threadIdx.x == 0) g_idx_is64 = ok;
    }
}

// ---------------------------------------------------------------------------
// histogram of destination rows
// ---------------------------------------------------------------------------
__global__ void hist_kernel(const void* __restrict__ edge_index) {
    int e = blockIdx.x * blockDim.x + threadIdx.x;
    if (e >= N_EDGES) return;
    int r;
    if (__ldg(&g_idx_is64)) r = (int)__ldg(&((const long long*)edge_index)[e]);
    else                    r = __ldg(&((const int*)edge_index)[e]);
    atomicAdd(&g_deg[r], 1);
}

// ---------------------------------------------------------------------------
// scan: per-block inclusive (scan1), parallel block-offset scan (scan2),
// combine (scan3)
// ---------------------------------------------------------------------------
__global__ void scan1_kernel() {
    __shared__ int sh[SCAN_BLK];
    int i = blockIdx.x * SCAN_BLK + threadIdx.x;
    int v = (i < N_TOTAL) ? g_deg[i] : 0;
    sh[threadIdx.x] = v;
    __syncthreads();
    for (int off = 1; off < SCAN_BLK; off <<= 1) {
        int t = (threadIdx.x >= off) ? sh[threadIdx.x - off] : 0;
        __syncthreads();
        sh[threadIdx.x] += t;
        __syncthreads();
    }
    if (i < N_TOTAL) g_incl[i] = sh[threadIdx.x];
    if (threadIdx.x == SCAN_BLK - 1) g_partials[blockIdx.x] = sh[SCAN_BLK - 1];
}

__global__ void scan2_kernel() {
    __shared__ int sh[256];
    int t = threadIdx.x;
    int v = (t < N_SCANBLK) ? g_partials[t] : 0;
    sh[t] = v;
    __syncthreads();
    for (int off = 1; off < 256; off <<= 1) {
        int u = (t >= off) ? sh[t - off] : 0;
        __syncthreads();
        sh[t] += u;
        __syncthreads();
    }
    if (t < N_SCANBLK) g_blockoff[t] = sh[t] - v;   // exclusive
}

__global__ void scan3_kernel() {
    int i = blockIdx.x * blockDim.x + threadIdx.x;
    if (i >= N_TOTAL) return;
    int incl = g_incl[i] + g_blockoff[i / SCAN_BLK];
    g_off[i + 1] = incl;
    g_cursor[i]  = incl - g_deg[i];
    if (i == 0) g_off[0] = 0;
}

// ---------------------------------------------------------------------------
// fill row-sorted packed edge array
// ---------------------------------------------------------------------------
__global__ void fill_kernel(const void* __restrict__ edge_index,
                            const float* __restrict__ edge_weight) {
    int e = blockIdx.x * blockDim.x + threadIdx.x;
    if (e >= N_EDGES) return;
    int r, c;
    if (__ldg(&g_idx_is64)) {
        const long long* ei = (const long long*)edge_index;
        r = (int)__ldg(&ei[e]);
        c = (int)__ldg(&ei[N_EDGES + e]);
    } else {
        const int* ei = (const int*)edge_index;
        r = __ldg(&ei[e]);
        c = __ldg(&ei[N_EDGES + e]);
    }
    int p = atomicAdd(&g_cursor[r], 1);
    g_cw[p] = make_int2(c, __float_as_int(__ldg(&edge_weight[e])));
}

// ---------------------------------------------------------------------------
// pull: 16 threads per node, lane j owns 4 features (one uint2 of half2s).
// Gather fp16, accumulate fp32.
// FINAL=0: write fp16 row to dst.
// FINAL=1: out = 0.25 * (x0_fp32 + h1 + h2 + a), fp32 output.
// ---------------------------------------------------------------------------
template <int FINAL>
__global__ void pull_kernel(const uint2* __restrict__ src,
                            uint2* __restrict__ dst,
                            const float4* __restrict__ eu,   // x0 user (fp32)
                            const float4* __restrict__ ei,   // x0 item (fp32)
                            const uint2* __restrict__ h1,
                            const uint2* __restrict__ h2,
                            float4* __restrict__ out) {
    int gid = blockIdx.x * blockDim.x + threadIdx.x;
    int n = gid >> 4;
    int j = gid & 15;
    if (n >= N_TOTAL) return;

    int s = __ldg(&g_off[n]);
    int t = __ldg(&g_off[n + 1]);

    float ax = 0.f, ay = 0.f, az = 0.f, aw = 0.f;
    int e = s;

#define EDGE_STEP(K)                                                          \
    {                                                                         \
        int2 cw = __ldg(&g_cw[e + K]);                                        \
        float w = __int_as_float(cw.y);                                       \
        uint2 p = __ldg(&src[(long long)cw.x * 16 + j]);                      \
        float2 f01 = __half22float2(*(__half2*)&p.x);                         \
        float2 f23 = __half22float2(*(__half2*)&p.y);                         \
        ax += f01.x * w; ay += f01.y * w;                                     \
        az += f23.x * w; aw += f23.y * w;                                     \
    }

    for (; e + 4 <= t; e += 4) {
        EDGE_STEP(0) EDGE_STEP(1) EDGE_STEP(2) EDGE_STEP(3)
    }
    for (; e < t; e++) {
        EDGE_STEP(0)
    }
#undef EDGE_STEP

    long long oi = (long long)n * 16 + j;
    if (FINAL) {
        float4 x0 = (n < N_USERS)
                        ? __ldg(&eu[oi])
                        : __ldg(&ei[(long long)(n - N_USERS) * 16 + j]);
        uint2 p1 = __ldg(&h1[oi]);
        uint2 p2 = __ldg(&h2[oi]);
        float2 a01 = __half22float2(*(__half2*)&p1.x);
        float2 a23 = __half22float2(*(__half2*)&p1.y);
        float2 b01 = __half22float2(*(__half2*)&p2.x);
        float2 b23 = __half22float2(*(__half2*)&p2.y);
        out[oi] = make_float4((x0.x + a01.x + b01.x + ax) * 0.25f,
                              (x0.y + a01.y + b01.y + ay) * 0.25f,
                              (x0.z + a23.x + b23.x + az) * 0.25f,
                              (x0.w + a23.y + b23.y + aw) * 0.25f);
    } else {
        dst[oi] = pack_h4(make_float4(ax, ay, az, aw));
    }
}

extern "C" void kernel_launch(void* const* d_in, const int* in_sizes, int n_in,
                              void* d_out, int out_size) {
    const void* edge_index   = d_in[0];
    const float* edge_weight = (const float*)d_in[1];
    const float4* user_emb   = (const float4*)d_in[2];
    const float4* item_emb   = (const float4*)d_in[3];
    float4* out              = (float4*)d_out;

    uint2 *h0, *h1, *h2;
    cudaGetSymbolAddress((void**)&h0, g_h0);
    cudaGetSymbolAddress((void**)&h1, g_h1);
    cudaGetSymbolAddress((void**)&h2, g_h2);

    const int TPB = 256;
    const int GRID_PREP = (N_F4 + TPB - 1) / TPB;
    const int GRID_EDGE = (N_EDGES + TPB - 1) / TPB;
    const int GRID_NODE = (N_TOTAL + TPB - 1) / TPB;
    const int GRID_PULL = (N_TOTAL * 16 + TPB - 1) / TPB;

    // prep: dtype detect + zero hist + x0 -> fp16
    prep_kernel<<<GRID_PREP, TPB>>>((const long long*)edge_index,
                                    user_emb, item_emb);

    // CSR build
    hist_kernel<<<GRID_EDGE, TPB>>>(edge_index);
    scan1_kernel<<<N_SCANBLK, SCAN_BLK>>>();
    scan2_kernel<<<1, 256>>>();
    scan3_kernel<<<GRID_NODE, TPB>>>();
    fill_kernel<<<GRID_EDGE, TPB>>>(edge_index, edge_weight);

    // h1 = A h0 ; h2 = A h1 ; out = 0.25*(x0 + h1 + h2 + A h2)
    pull_kernel<0><<<GRID_PULL, TPB>>>(h0, h1, nullptr, nullptr,
                                       nullptr, nullptr, nullptr);
    pull_kernel<0><<<GRID_PULL, TPB>>>(h1, h2, nullptr, nullptr,
                                       nullptr, nullptr, nullptr);
    pull_kernel<1><<<GRID_PULL, TPB>>>(h2, nullptr, user_emb, item_emb,
                                       h1, h2, out);
}